// round 17
// baseline (speedup 1.0000x reference)
#include <cuda_runtime.h>
#include <cuda_fp16.h>
#include <stdint.h>

#define RES 512
#define PR  514           // padded resolution: 1-texel zero ring
#define CH  32
#define PLANE_PAD_ELEMS (PR * PR * CH)

// Zero-padded (H, W, C) fp16 planes. Texel = 32 halves = 64B.
// Interior texel (y, x) lives at padded coords (y+1, x+1).
__device__ __align__(128) __half g_TP[3][PLANE_PAD_ELEMS];

// ---------------------------------------------------------------------------
// Prep: transpose (C,H,W) fp32 -> padded (H,W,C) fp16, border-ring zeroing
// folded into the blockIdx.y==0 blocks. grid=(RES, RES/32, 3), block=(32,8).
// (unchanged from R15 — measured at its compulsory-traffic floor)
// ---------------------------------------------------------------------------
__global__ __launch_bounds__(256) void triplane_prep_kernel(
    const float* __restrict__ t_xy,
    const float* __restrict__ t_yz,
    const float* __restrict__ t_zx)
{
    __shared__ float tile[32][33];   // [channel][x-in-tile]

    const int y  = blockIdx.x;
    const int x0 = blockIdx.y * 32;
    const int p  = blockIdx.z;
    const int tx = threadIdx.x;      // 0..31
    const int ty = threadIdx.y;      // 0..7
    const int tid = ty * 32 + tx;

    const float* src = (p == 0) ? t_xy : (p == 1) ? t_yz : t_zx;
    const float* sp = src + y * RES + x0 + tx;

#pragma unroll
    for (int i = 0; i < 4; ++i) {
        const int c = ty + 8 * i;
        tile[c][tx] = sp[c * (RES * RES)];   // coalesced, MLP=4
    }

    // Border zeroing: 2052 ring texels/plane spread over the 512 y-blocks.
    if (blockIdx.y == 0) {
        const int nt = (y == RES - 1) ? 32 : 16;
        if (tid < nt) {
            const int b   = 4 * y + (tid >> 2);   // ring texel index < 2052
            const int seg = tid & 3;
            int by, bx;
            if (b < PR)                 { by = 0;                    bx = b; }
            else if (b < 2 * PR)        { by = PR - 1;               bx = b - PR; }
            else if (b < 2 * PR + RES)  { by = b - 2 * PR + 1;       bx = 0; }
            else                        { by = b - (2 * PR + RES) + 1; bx = PR - 1; }
            *(uint4*)(g_TP[p] + ((size_t)by * PR + bx) * CH + seg * 8) =
                make_uint4(0u, 0u, 0u, 0u);
        }
    }
    __syncthreads();

    if (tid < 128) {
        const int xx  = tid >> 2;        // texel within tile (0..31)
        const int seg = tid & 3;         // 16B segment of the 64B texel

        uint4 v;
#pragma unroll
        for (int j = 0; j < 4; ++j) {
            const int c = seg * 8 + 2 * j;
            ((__half2*)&v)[j] = __floats2half2_rn(tile[c][xx], tile[c + 1][xx]);
        }
        *(uint4*)(g_TP[p] + ((size_t)(y + 1) * PR + (x0 + xx + 1)) * CH + seg * 8) = v;
    }
}

// ---------------------------------------------------------------------------
// Cache-policy helpers (legal sm_103 encodings; R15-validated).
// ---------------------------------------------------------------------------
__device__ __forceinline__ uint64_t mk_evict_last_policy()
{
    uint64_t pol;
    asm("createpolicy.fractional.L2::evict_last.b64 %0, 1.0;" : "=l"(pol));
    return pol;
}
__device__ __forceinline__ uint4 ldg_el(const __half* p, uint64_t pol)
{
    uint4 v;
    asm volatile("ld.global.nc.L2::cache_hint.v4.u32 {%0,%1,%2,%3}, [%4], %5;"
                 : "=r"(v.x), "=r"(v.y), "=r"(v.z), "=r"(v.w)
                 : "l"(p), "l"(pol));
    return v;
}
__device__ __forceinline__ void stg_cs2(float* p, float2 v)
{
    asm volatile("st.global.cs.v2.f32 [%0], {%1,%2};"
                 :: "l"(p), "f"(v.x), "f"(v.y) : "memory");
}

// ---------------------------------------------------------------------------
// Sampling: 16 lanes per point. Lane s (0..15): ysel = s>>3 (row),
// xsel = (s>>2)&1 (x corner), chunk = s&3 (8 channels). Each lane issues ONE
// uint4 load per plane -> only 3 LDG/thread, ~4 v-regs live, so all 3 plane
// loads stay in flight within the full-occupancy register budget (the queue-
// supply fix R11 tried to buy with registers). Lines/pt unchanged (9.25).
// Epilogue: 2-stage half2 shfl reduce (xor4 = x corners, xor8 = rows).
// ---------------------------------------------------------------------------
__global__ __launch_bounds__(256) void triplane_sample_kernel(
    const float* __restrict__ xyz,
    float* __restrict__ out,
    int npts)
{
    const int gtid  = blockIdx.x * blockDim.x + threadIdx.x;
    const int pid   = gtid >> 4;
    const int s     = gtid & 15;
    const int chunk = s & 3;
    const int xsel  = (s >> 2) & 1;
    const int ysel  = s >> 3;

    // Warp-cooperative coord load: warp covers 2 points -> 6 floats.
    const int lane = threadIdx.x & 31;
    const int wbase_pt = (blockIdx.x * blockDim.x + (threadIdx.x & ~31)) >> 4;
    float cv = 0.f;
    {
        const int ci = wbase_pt * 3 + lane;
        if (lane < 6 && ci < npts * 3) cv = __ldg(xyz + ci);
    }
    const int pg3 = (lane >> 4) * 3;
    const float cx = __shfl_sync(0xffffffffu, cv, pg3 + 0);
    const float cy = __shfl_sync(0xffffffffu, cv, pg3 + 1);
    const float cz = __shfl_sync(0xffffffffu, cv, pg3 + 2);

    if (pid >= npts) return;

    const uint64_t pol = mk_evict_last_policy();

    // f_xy: (X, Y)   f_yz: (Y, Z)   f_zx: (Z, X)
    const float cA[3] = {cx, cy, cz};   // W coordinate
    const float cB[3] = {cy, cz, cx};   // H coordinate

    const int laneoff = chunk * 8;      // this lane's 8-channel offset (halves)

    __half2 acc[4];
    const __half2 hz = __float2half2_rn(0.f);
#pragma unroll
    for (int j = 0; j < 4; ++j) acc[j] = hz;

#pragma unroll
    for (int p = 0; p < 3; ++p) {
        // padded pixel coord = 256*c + 256.5; c in [-1,1) -> [0.5, 512.5):
        // floor indices in [0,512], no clamps, no masks.
        const float xf = fmaf(cA[p], 256.0f, 256.5f);
        const float yf = fmaf(cB[p], 256.0f, 256.5f);

        const float x0f = floorf(xf);
        const float y0f = floorf(yf);
        const float wx1 = xf - x0f;
        const float wy1 = yf - y0f;

        const int ixp = (int)x0f;
        const int iyp = (int)y0f;

        // this lane's single corner weight (one cvt per plane)
        const float wxl = xsel ? wx1 : (1.0f - wx1);
        const float wyl = ysel ? wy1 : (1.0f - wy1);
        const __half2 wh = __float2half2_rn(wyl * wxl);

        // one uint4 load per plane: row (iyp+ysel), texel (ixp+xsel)
        const __half* t = g_TP[p]
            + (size_t)((iyp + ysel) * PR + ixp + xsel) * CH + laneoff;
        const uint4 v = ldg_el(t, pol);

        const __half2* h = (const __half2*)&v;
#pragma unroll
        for (int j = 0; j < 4; ++j)
            acc[j] = __hfma2(h[j], wh, acc[j]);
    }

    // Reduce across x corners (xor 4) then rows (xor 8), in half2.
#pragma unroll
    for (int j = 0; j < 4; ++j) {
        uint32_t o = __shfl_xor_sync(0xffffffffu, *(const uint32_t*)&acc[j], 4);
        acc[j] = __hadd2(acc[j], *(const __half2*)&o);
        o = __shfl_xor_sync(0xffffffffu, *(const uint32_t*)&acc[j], 8);
        acc[j] = __hadd2(acc[j], *(const __half2*)&o);
    }

    // All 16 lanes now hold the full 8-channel result for their chunk,
    // replicated 4x. Lane 'sub' = s>>2 (0..3) stores float2 #sub of the chunk.
    // Warp = 2 points x 128B contiguous.
    const int sub = s >> 2;
    __half2 pick = acc[0];
    pick = (sub == 1) ? acc[1] : pick;
    pick = (sub == 2) ? acc[2] : pick;
    pick = (sub == 3) ? acc[3] : pick;
    stg_cs2(out + (size_t)pid * CH + chunk * 8 + sub * 2,
            __half22float2(pick));
}

// ---------------------------------------------------------------------------
// kernel_launch
// inputs: xyz [N*3], T_xy, T_yz, T_zx [1*32*512*512] fp32 ; output [N*32] fp32
// ---------------------------------------------------------------------------
extern "C" void kernel_launch(void* const* d_in, const int* in_sizes, int n_in,
                              void* d_out, int out_size)
{
    const float* xyz  = (const float*)d_in[0];
    const float* t_xy = (const float*)d_in[1];
    const float* t_yz = (const float*)d_in[2];
    const float* t_zx = (const float*)d_in[3];
    float* out = (float*)d_out;

    const int npts = in_sizes[0] / 3;

    // 1) transpose + fp16 convert + border zeroing, one launch
    dim3 tgrid(RES, RES / 32, 3);
    dim3 tblock(32, 8);
    triplane_prep_kernel<<<tgrid, tblock>>>(t_xy, t_yz, t_zx);

    // 2) sample: 16 threads per point
    const long long total = (long long)npts * 16;
    const int block = 256;
    const int grid = (int)((total + block - 1) / block);
    triplane_sample_kernel<<<grid, block>>>(xyz, out, npts);
}